// round 4
// baseline (speedup 1.0000x reference)
#include <cuda_runtime.h>
#include <math.h>

#define NB 48
#define CC 512
#define PP 1600
#define KK 64
#define EPSV 1e-12f

typedef unsigned long long ull;

// Scratch (device globals; no allocations allowed). 16B-aligned for float2/float4 access.
__device__ __align__(16) float g_w[NB * KK * PP];      // soft_assign * hmp   [n][k][p]
__device__ __align__(16) float g_invn[NB * PP];        // 1/max(||x||, eps) per pixel
__device__ __align__(16) float g_hmp[NB * PP];         // attention heatmap per pixel
__device__ __align__(16) float g_wsum[NB * KK];        // sum_p w
__device__ __align__(16) float g_knss[NB * KK];        // per-(n,k) sumsq of intra-normed vec

// packed fp32x2 FMA: d = a*b + d (lane-wise). Only reachable via PTX (SASS FFMA2).
#define FFMA2(d, a, b) \
    asm("fma.rn.f32x2 %0, %1, %2, %0;" : "+l"(d) : "l"(a), "l"(b))

__device__ __forceinline__ ull dup_f32x2(float v) {
    ull d;
    asm("mov.b64 %0, {%1, %1};" : "=l"(d) : "f"(v));
    return d;
}
__device__ __forceinline__ float lo32(ull v) { return __uint_as_float((unsigned)v); }
__device__ __forceinline__ float hi32(ull v) { return __uint_as_float((unsigned)(v >> 32)); }

// ---------------------------------------------------------------------------
// K1: per-pixel channel stats: invn and heatmap. One coalesced pass over x.
// ---------------------------------------------------------------------------
__global__ void k_pixstats(const float* __restrict__ x,
                           const float* __restrict__ aw,
                           const float* __restrict__ ab) {
    __shared__ float saw[CC];
    int t = threadIdx.x;
    for (int i = t; i < CC; i += 256) saw[i] = aw[i];
    __syncthreads();

    int pix = blockIdx.x * 256 + t;              // 76800 total = 300 * 256
    int n = pix / PP;
    int p = pix - n * PP;
    const float* xp = x + (size_t)n * CC * PP + p;

    float ss = 0.f, av = 0.f;
#pragma unroll 8
    for (int c = 0; c < CC; c++) {
        float v = xp[(size_t)c * PP];
        ss = fmaf(v, v, ss);
        float r = v > 0.f ? v : 0.f;
        av = fmaf(r, saw[c], av);
    }
    float hm = av + ab[0];
    hm = hm > 0.f ? hm : 0.f;
    float invn = 1.f / fmaxf(sqrtf(ss), EPSV);
    g_invn[pix] = invn;
    g_hmp[pix] = hm;
}

// ---------------------------------------------------------------------------
// K2: logits GEMM (64k x 512c) x (512c x 64p tile) + softmax over k + w.
// 128 threads, micro-tile 4k x 8p (4 f32x2 pairs). Grid (25, 48) — exact, no guards.
// ---------------------------------------------------------------------------
__global__ void __launch_bounds__(128) k_assign(const float* __restrict__ x,
                                                const float* __restrict__ cw) {
    __shared__ ull   ws2[16][65];     // [c-chunk][k], duplicated f32x2, padded
    __shared__ float xs[16][64];      // [c-chunk][p] (reused for softmax reductions)
    __shared__ float cm[64];
    __shared__ float cs[64];

    int t = threadIdx.x;
    int tx = t & 7;                   // p group: p = tx*8 + j (8 contiguous)
    int ty = t >> 3;                  // 0..15   k = ty + 16*i
    int n = blockIdx.y;
    int p0 = blockIdx.x * 64;
    const float* xb = x + (size_t)n * CC * PP;

    ull acc[4][4];
#pragma unroll
    for (int i = 0; i < 4; i++)
#pragma unroll
        for (int u = 0; u < 4; u++) acc[i][u] = 0ull;

    for (int c0 = 0; c0 < CC; c0 += 16) {
#pragma unroll
        for (int q = 0; q < 8; q++) {            // conv_w tile: 64k x 16c, duplicated
            int e = t + q * 128;
            int k = e >> 4, cc = e & 15;
            ws2[cc][k] = dup_f32x2(cw[k * CC + c0 + cc]);
        }
#pragma unroll
        for (int q = 0; q < 8; q++) {            // x tile: 16c x 64p
            int e = t + q * 128;
            int cc = e >> 6, pp = e & 63;
            xs[cc][pp] = xb[(size_t)(c0 + cc) * PP + p0 + pp];
        }
        __syncthreads();
#pragma unroll
        for (int cc = 0; cc < 16; cc++) {
            ull a[4], b[4];
#pragma unroll
            for (int i = 0; i < 4; i++) a[i] = ws2[cc][ty + 16 * i];
#pragma unroll
            for (int u = 0; u < 4; u++)
                b[u] = *reinterpret_cast<const ull*>(&xs[cc][tx * 8 + 2 * u]);
#pragma unroll
            for (int i = 0; i < 4; i++)
#pragma unroll
                for (int u = 0; u < 4; u++) FFMA2(acc[i][u], a[i], b[u]);
        }
        __syncthreads();
    }

    // unpack and scale by invn[p]
    const float2* invp = reinterpret_cast<const float2*>(g_invn + n * PP + p0 + tx * 8);
    const float2* hmpp = reinterpret_cast<const float2*>(g_hmp + n * PP + p0 + tx * 8);
    float f[4][8], hm[8];
#pragma unroll
    for (int u = 0; u < 4; u++) {
        float2 iv = invp[u];
        float2 hv = hmpp[u];
        hm[2 * u] = hv.x; hm[2 * u + 1] = hv.y;
#pragma unroll
        for (int i = 0; i < 4; i++) {
            f[i][2 * u]     = lo32(acc[i][u]) * iv.x;
            f[i][2 * u + 1] = hi32(acc[i][u]) * iv.y;
        }
    }

    // softmax over k: partial max per thread (4 k's) -> 16 rows -> column reduce
#pragma unroll
    for (int j = 0; j < 8; j++) {
        float m = f[0][j];
#pragma unroll
        for (int i = 1; i < 4; i++) m = fmaxf(m, f[i][j]);
        xs[ty][tx * 8 + j] = m;
    }
    __syncthreads();
    if (t < 64) {
        float m = -1e30f;
#pragma unroll
        for (int r = 0; r < 16; r++) m = fmaxf(m, xs[r][t]);
        cm[t] = m;
    }
    __syncthreads();
#pragma unroll
    for (int j = 0; j < 8; j++) {
        float m = cm[tx * 8 + j];
        float s = 0.f;
#pragma unroll
        for (int i = 0; i < 4; i++) {
            f[i][j] = __expf(f[i][j] - m);
            s += f[i][j];
        }
        xs[ty][tx * 8 + j] = s;
    }
    __syncthreads();
    if (t < 64) {
        float s = 0.f;
#pragma unroll
        for (int r = 0; r < 16; r++) s += xs[r][t];
        cs[t] = s;
    }
    __syncthreads();

    float* wb = g_w + (size_t)n * KK * PP;
    float sc[8];
#pragma unroll
    for (int j = 0; j < 8; j++) sc[j] = hm[j] / cs[tx * 8 + j];
#pragma unroll
    for (int i = 0; i < 4; i++) {
        float* row = wb + (size_t)(ty + 16 * i) * PP + p0 + tx * 8;
#pragma unroll
        for (int u = 0; u < 4; u++) {
            float2 v;
            v.x = f[i][2 * u]     * sc[2 * u];
            v.y = f[i][2 * u + 1] * sc[2 * u + 1];
            reinterpret_cast<float2*>(row)[u] = v;
        }
    }
}

// ---------------------------------------------------------------------------
// K3: term1 GEMM: (64k x 1600p) x (1600p x 64c tile) -> term1[k,c];
// invn folded into x side; wsum computed by c-tile-0 blocks. Grid (8, 48), 128 thr.
// ---------------------------------------------------------------------------
__global__ void __launch_bounds__(128) k_vladgemm(const float* __restrict__ x,
                                                  float* __restrict__ out) {
    __shared__ ull   ws2[16][65];     // [p-chunk][k], duplicated f32x2
    __shared__ float xs2[16][66];     // [p-chunk][c], padded (even pad -> 8B aligned rows)
    __shared__ float invs[PP];

    int t = threadIdx.x;
    int tx = t & 7;                   // c group: c = c0 + tx*8 + j
    int ty = t >> 3;                  // k = ty + 16*i
    int cb = blockIdx.x, n = blockIdx.y;
    int c0 = cb * 64;
    const float* xb = x + (size_t)n * CC * PP;
    const float* wb = g_w + (size_t)n * KK * PP;

    for (int i = t; i < PP; i += 128) invs[i] = g_invn[n * PP + i];

    ull acc[4][4];
#pragma unroll
    for (int i = 0; i < 4; i++)
#pragma unroll
        for (int u = 0; u < 4; u++) acc[i][u] = 0ull;
    float wl = 0.f;
    __syncthreads();

    for (int p0 = 0; p0 < PP; p0 += 16) {
#pragma unroll
        for (int q = 0; q < 8; q++) {            // w tile: 64k x 16p, duplicated
            int e = t + q * 128;
            int k = e >> 4, pp = e & 15;
            ws2[pp][k] = dup_f32x2(wb[(size_t)k * PP + p0 + pp]);
        }
#pragma unroll
        for (int q = 0; q < 8; q++) {            // x tile: 64c x 16p transposed, scaled
            int e = t + q * 128;
            int cl = e >> 4, pp = e & 15;
            xs2[pp][cl] = xb[(size_t)(c0 + cl) * PP + p0 + pp] * invs[p0 + pp];
        }
        __syncthreads();
        if (cb == 0 && t < 64) {
#pragma unroll
            for (int pp = 0; pp < 16; pp++)
                wl += *reinterpret_cast<const float*>(&ws2[pp][t]);  // low half
        }
#pragma unroll
        for (int pp = 0; pp < 16; pp++) {
            ull a[4], b[4];
#pragma unroll
            for (int i = 0; i < 4; i++) a[i] = ws2[pp][ty + 16 * i];
#pragma unroll
            for (int u = 0; u < 4; u++)
                b[u] = *reinterpret_cast<const ull*>(&xs2[pp][tx * 8 + 2 * u]);
#pragma unroll
            for (int i = 0; i < 4; i++)
#pragma unroll
                for (int u = 0; u < 4; u++) FFMA2(acc[i][u], a[i], b[u]);
        }
        __syncthreads();
    }

    float* ob = out + (size_t)n * KK * CC;
#pragma unroll
    for (int i = 0; i < 4; i++) {
        float* row = ob + (size_t)(ty + 16 * i) * CC + c0 + tx * 8;
#pragma unroll
        for (int u = 0; u < 4; u++) {
            float2 v;
            v.x = lo32(acc[i][u]);
            v.y = hi32(acc[i][u]);
            reinterpret_cast<float2*>(row)[u] = v;
        }
    }
    if (cb == 0 && t < 64) g_wsum[n * KK + t] = wl;
}

// ---------------------------------------------------------------------------
// K4: vlad = term1 - wsum*centroid, intra-L2-norm per (n,k). 3072 blocks x 128.
// ---------------------------------------------------------------------------
__global__ void k_intranorm(float* __restrict__ out,
                            const float* __restrict__ cent) {
    int nk = blockIdx.x;
    int k = nk & 63;
    int t = threadIdx.x;
    float wsv = g_wsum[nk];
    size_t base = (size_t)nk * CC;
    const float* cb = cent + (size_t)k * CC;

    float v[4];
    float ss = 0.f;
#pragma unroll
    for (int q = 0; q < 4; q++) {
        int c = t + 128 * q;
        v[q] = out[base + c] - wsv * cb[c];
        ss = fmaf(v[q], v[q], ss);
    }
#pragma unroll
    for (int o = 16; o > 0; o >>= 1) ss += __shfl_xor_sync(0xffffffffu, ss, o);
    __shared__ float sred[4];
    if ((t & 31) == 0) sred[t >> 5] = ss;
    __syncthreads();
    float tot = sred[0] + sred[1] + sred[2] + sred[3];
    float invv = 1.f / fmaxf(sqrtf(tot), EPSV);
#pragma unroll
    for (int q = 0; q < 4; q++) out[base + t + 128 * q] = v[q] * invv;
    if (t == 0) g_knss[nk] = tot * invv * invv;
}

// ---------------------------------------------------------------------------
// K5: global L2 norm per n. Grid (48, 16), 2048 elems per block.
// ---------------------------------------------------------------------------
__global__ void k_globalnorm(float* __restrict__ out) {
    int n = blockIdx.x, t = threadIdx.x;
    float gs = 0.f;
#pragma unroll
    for (int i = 0; i < KK; i++) gs += g_knss[n * KK + i];
    float sc = 1.f / fmaxf(sqrtf(gs), EPSV);
    size_t base = (size_t)n * KK * CC + (size_t)blockIdx.y * 2048;
#pragma unroll
    for (int q = 0; q < 8; q++) out[base + t + 256 * q] *= sc;
}

// ---------------------------------------------------------------------------
extern "C" void kernel_launch(void* const* d_in, const int* in_sizes, int n_in,
                              void* d_out, int out_size) {
    const float* x  = (const float*)d_in[0];   // [48,512,40,40]
    const float* cw = (const float*)d_in[1];   // [64,512]
    const float* aw = (const float*)d_in[2];   // [1,512]
    const float* ab = (const float*)d_in[3];   // [1]
    const float* ct = (const float*)d_in[4];   // [64,512]
    float* out = (float*)d_out;                // [48, 32768]

    k_pixstats<<<300, 256>>>(x, aw, ab);
    k_assign<<<dim3(25, 48), 128>>>(x, cw);
    k_vladgemm<<<dim3(8, 48), 128>>>(x, out);
    k_intranorm<<<NB * KK, 128>>>(out, ct);
    k_globalnorm<<<dim3(48, 16), 256>>>(out);
}

// round 7
// speedup vs baseline: 1.3317x; 1.3317x over previous
#include <cuda_runtime.h>
#include <math.h>

#define NB 48
#define CC 512
#define PP 1600
#define KK 64
#define EPSV 1e-12f

typedef unsigned long long ull;

// Scratch (device globals; no allocations allowed).
__device__ __align__(16) float g_w[NB * KK * PP];      // soft_assign * hmp   [n][k][p]
__device__ __align__(16) float g_invn[NB * PP];        // 1/max(||x||, eps) per pixel
__device__ __align__(16) float g_hmp[NB * PP];         // attention heatmap per pixel
__device__ __align__(16) float g_wsum[NB * KK];        // sum_p w
__device__ __align__(16) float g_knss[NB * KK];        // per-(n,k) sumsq of intra-normed vec

// packed fp32x2 FMA: d = a*b + d (lane-wise). SASS FFMA2, only via PTX.
#define FFMA2(d, a, b) \
    asm("fma.rn.f32x2 %0, %1, %2, %0;" : "+l"(d) : "l"(a), "l"(b))

__device__ __forceinline__ ull dup_f32x2(float v) {
    ull d;
    asm("mov.b64 %0, {%1, %1};" : "=l"(d) : "f"(v));
    return d;
}
__device__ __forceinline__ float lo32(ull v) { return __uint_as_float((unsigned)v); }
__device__ __forceinline__ float hi32(ull v) { return __uint_as_float((unsigned)(v >> 32)); }

// pair-interleaved float index for value idx within a 64-wide tile dimension:
// value v (0..63) decomposed v = g*8 + 2*j + h  (g = v>>3, j = (v>>1)&3, h = v&1)
// lives at float offset j*16 + g*2 + h  == ull slot (j*8 + g), half h.
__device__ __forceinline__ int pair_idx(int v) {
    return (v & 1) + ((v >> 1) & 3) * 16 + ((v >> 3) << 1);
}

// ---------------------------------------------------------------------------
// K1: per-pixel channel stats: invn and heatmap. One coalesced pass over x.
// ---------------------------------------------------------------------------
__global__ void k_pixstats(const float* __restrict__ x,
                           const float* __restrict__ aw,
                           const float* __restrict__ ab) {
    __shared__ float saw[CC];
    int t = threadIdx.x;
    for (int i = t; i < CC; i += 256) saw[i] = aw[i];
    __syncthreads();

    int pix = blockIdx.x * 256 + t;              // 76800 total = 300 * 256
    int n = pix / PP;
    int p = pix - n * PP;
    const float* xp = x + (size_t)n * CC * PP + p;

    float ss = 0.f, av = 0.f;
#pragma unroll 8
    for (int c = 0; c < CC; c++) {
        float v = xp[(size_t)c * PP];
        ss = fmaf(v, v, ss);
        float r = v > 0.f ? v : 0.f;
        av = fmaf(r, saw[c], av);
    }
    float hm = av + ab[0];
    hm = hm > 0.f ? hm : 0.f;
    float invn = 1.f / fmaxf(sqrtf(ss), EPSV);
    g_invn[pix] = invn;
    g_hmp[pix] = hm;
}

// ---------------------------------------------------------------------------
// K2: logits GEMM (64k x 512c)x(512c x 64p) + softmax over k + w.
// 64 threads, micro-tile 8k x 8p, f32x2 FMA, pair-packed smem. Grid (25,48).
// ---------------------------------------------------------------------------
__global__ void __launch_bounds__(64) k_assign(const float* __restrict__ x,
                                               const float* __restrict__ cw) {
    __shared__ ull   ws[32][33];      // [cc][j*8+g] = {cw[k=g*8+2j], cw[k+1]}
    __shared__ ull   xs[32][33];      // [cc][u*8+g] = {x[p=g*8+2u],  x[p+1]}
    __shared__ float red[8][64];
    __shared__ float cm[64];
    __shared__ float cs[64];

    int t = threadIdx.x;
    int tx = t & 7;                   // p group: p = tx*8 + (0..7)
    int ty = t >> 3;                  // k group: k = ty*8 + (0..7)
    int n = blockIdx.y;
    int p0 = blockIdx.x * 64;
    const float* xb = x + (size_t)n * CC * PP;

    ull acc[8][4];
#pragma unroll
    for (int i = 0; i < 8; i++)
#pragma unroll
        for (int u = 0; u < 4; u++) acc[i][u] = 0ull;

    for (int c0 = 0; c0 < CC; c0 += 32) {
#pragma unroll
        for (int q = 0; q < 32; q++) {           // conv_w tile: 64k x 32c
            int e = t + q * 64;
            int k = e >> 5, cc = e & 31;
            ((float*)ws[cc])[pair_idx(k)] = cw[k * CC + c0 + cc];
        }
#pragma unroll
        for (int q = 0; q < 32; q++) {           // x tile: 32c x 64p
            int e = t + q * 64;
            int cc = e >> 6, p = e & 63;
            ((float*)xs[cc])[pair_idx(p)] = xb[(size_t)(c0 + cc) * PP + p0 + p];
        }
        __syncthreads();
#pragma unroll 4
        for (int cc = 0; cc < 32; cc++) {
            ull ap[4], b[4], ad[8];
#pragma unroll
            for (int j = 0; j < 4; j++) ap[j] = ws[cc][j * 8 + ty];
#pragma unroll
            for (int u = 0; u < 4; u++) b[u] = xs[cc][u * 8 + tx];
#pragma unroll
            for (int j = 0; j < 4; j++) {
                ad[2 * j]     = dup_f32x2(lo32(ap[j]));
                ad[2 * j + 1] = dup_f32x2(hi32(ap[j]));
            }
#pragma unroll
            for (int i = 0; i < 8; i++)
#pragma unroll
                for (int u = 0; u < 4; u++) FFMA2(acc[i][u], ad[i], b[u]);
        }
        __syncthreads();
    }

    // unpack + scale by invn[p]   (p = tx*8 + j, j = 2u+h)
    const float2* invp = reinterpret_cast<const float2*>(g_invn + n * PP + p0 + tx * 8);
    const float2* hmpp = reinterpret_cast<const float2*>(g_hmp + n * PP + p0 + tx * 8);
    float f[8][8], hm[8];
#pragma unroll
    for (int u = 0; u < 4; u++) {
        float2 iv = invp[u];
        float2 hv = hmpp[u];
        hm[2 * u] = hv.x; hm[2 * u + 1] = hv.y;
#pragma unroll
        for (int i = 0; i < 8; i++) {
            f[i][2 * u]     = lo32(acc[i][u]) * iv.x;
            f[i][2 * u + 1] = hi32(acc[i][u]) * iv.y;
        }
    }

    // softmax over k = 64 (8 local x 8 ty groups)
#pragma unroll
    for (int j = 0; j < 8; j++) {
        float m = f[0][j];
#pragma unroll
        for (int i = 1; i < 8; i++) m = fmaxf(m, f[i][j]);
        red[ty][tx * 8 + j] = m;
    }
    __syncthreads();
    {
        float m = red[0][t];
#pragma unroll
        for (int r = 1; r < 8; r++) m = fmaxf(m, red[r][t]);
        cm[t] = m;
    }
    __syncthreads();
#pragma unroll
    for (int j = 0; j < 8; j++) {
        float m = cm[tx * 8 + j];
        float s = 0.f;
#pragma unroll
        for (int i = 0; i < 8; i++) {
            f[i][j] = __expf(f[i][j] - m);
            s += f[i][j];
        }
        red[ty][tx * 8 + j] = s;
    }
    __syncthreads();
    {
        float s = red[0][t];
#pragma unroll
        for (int r = 1; r < 8; r++) s += red[r][t];
        cs[t] = s;
    }
    __syncthreads();

    float* wb = g_w + (size_t)n * KK * PP;
    float sc[8];
#pragma unroll
    for (int j = 0; j < 8; j++) sc[j] = hm[j] / cs[tx * 8 + j];
#pragma unroll
    for (int i = 0; i < 8; i++) {
        float* row = wb + (size_t)(ty * 8 + i) * PP + p0 + tx * 8;
#pragma unroll
        for (int u = 0; u < 4; u++) {
            float2 v;
            v.x = f[i][2 * u]     * sc[2 * u];
            v.y = f[i][2 * u + 1] * sc[2 * u + 1];
            reinterpret_cast<float2*>(row)[u] = v;
        }
    }
}

// ---------------------------------------------------------------------------
// K3: term1 GEMM: (64k x 1600p)x(1600p x 64c) -> term1[k,c]; invn folded into
// x side; wsum computed by c-tile-0 blocks. 64 threads, 8k x 8c tile. Grid (8,48).
// ---------------------------------------------------------------------------
__global__ void __launch_bounds__(64) k_vladgemm(const float* __restrict__ x,
                                                 float* __restrict__ out) {
    __shared__ ull   wsp[32][33];     // [pp][j*8+g] = {w[k=g*8+2j], w[k+1]}
    __shared__ ull   xsc[32][33];     // [pp][u*8+g] = {xn[c=g*8+2u], xn[c+1]}
    __shared__ float invs[PP];

    int t = threadIdx.x;
    int tx = t & 7;                   // c group
    int ty = t >> 3;                  // k group
    int cb = blockIdx.x, n = blockIdx.y;
    int c0 = cb * 64;
    const float* xb = x + (size_t)n * CC * PP;
    const float* wb = g_w + (size_t)n * KK * PP;

    for (int i = t; i < PP; i += 64) invs[i] = g_invn[n * PP + i];

    ull acc[8][4];
#pragma unroll
    for (int i = 0; i < 8; i++)
#pragma unroll
        for (int u = 0; u < 4; u++) acc[i][u] = 0ull;
    float wl = 0.f;
    int idx_t = pair_idx(t);          // for wsum readback (t = k)
    __syncthreads();

    for (int p0 = 0; p0 < PP; p0 += 32) {
#pragma unroll
        for (int q = 0; q < 32; q++) {           // w tile: 64k x 32p
            int e = t + q * 64;
            int k = e >> 5, pp = e & 31;
            ((float*)wsp[pp])[pair_idx(k)] = wb[(size_t)k * PP + p0 + pp];
        }
#pragma unroll
        for (int q = 0; q < 32; q++) {           // x tile: 64c x 32p, scaled
            int e = t + q * 64;
            int cl = e >> 5, pp = e & 31;
            ((float*)xsc[pp])[pair_idx(cl)] =
                xb[(size_t)(c0 + cl) * PP + p0 + pp] * invs[p0 + pp];
        }
        __syncthreads();
        if (cb == 0) {
#pragma unroll 8
            for (int pp = 0; pp < 32; pp++) wl += ((float*)wsp[pp])[idx_t];
        }
#pragma unroll 4
        for (int pp = 0; pp < 32; pp++) {
            ull ap[4], b[4], ad[8];
#pragma unroll
            for (int j = 0; j < 4; j++) ap[j] = wsp[pp][j * 8 + ty];
#pragma unroll
            for (int u = 0; u < 4; u++) b[u] = xsc[pp][u * 8 + tx];
#pragma unroll
            for (int j = 0; j < 4; j++) {
                ad[2 * j]     = dup_f32x2(lo32(ap[j]));
                ad[2 * j + 1] = dup_f32x2(hi32(ap[j]));
            }
#pragma unroll
            for (int i = 0; i < 8; i++)
#pragma unroll
                for (int u = 0; u < 4; u++) FFMA2(acc[i][u], ad[i], b[u]);
        }
        __syncthreads();
    }

    float* ob = out + (size_t)n * KK * CC;
#pragma unroll
    for (int i = 0; i < 8; i++) {
        float* row = ob + (size_t)(ty * 8 + i) * CC + c0 + tx * 8;
#pragma unroll
        for (int u = 0; u < 4; u++) {
            float2 v;
            v.x = lo32(acc[i][u]);
            v.y = hi32(acc[i][u]);
            reinterpret_cast<float2*>(row)[u] = v;
        }
    }
    if (cb == 0) g_wsum[n * KK + t] = wl;
}

// ---------------------------------------------------------------------------
// K4: vlad = term1 - wsum*centroid, intra-L2-norm per (n,k). 3072 blocks x 128.
// ---------------------------------------------------------------------------
__global__ void k_intranorm(float* __restrict__ out,
                            const float* __restrict__ cent) {
    int nk = blockIdx.x;
    int k = nk & 63;
    int t = threadIdx.x;
    float wsv = g_wsum[nk];
    size_t base = (size_t)nk * CC;
    const float* cb = cent + (size_t)k * CC;

    float v[4];
    float ss = 0.f;
#pragma unroll
    for (int q = 0; q < 4; q++) {
        int c = t + 128 * q;
        v[q] = out[base + c] - wsv * cb[c];
        ss = fmaf(v[q], v[q], ss);
    }
#pragma unroll
    for (int o = 16; o > 0; o >>= 1) ss += __shfl_xor_sync(0xffffffffu, ss, o);
    __shared__ float sred[4];
    if ((t & 31) == 0) sred[t >> 5] = ss;
    __syncthreads();
    float tot = sred[0] + sred[1] + sred[2] + sred[3];
    float invv = 1.f / fmaxf(sqrtf(tot), EPSV);
#pragma unroll
    for (int q = 0; q < 4; q++) out[base + t + 128 * q] = v[q] * invv;
    if (t == 0) g_knss[nk] = tot * invv * invv;
}

// ---------------------------------------------------------------------------
// K5: global L2 norm per n. Grid (48, 16), 2048 elems per block.
// ---------------------------------------------------------------------------
__global__ void k_globalnorm(float* __restrict__ out) {
    int n = blockIdx.x, t = threadIdx.x;
    float gs = 0.f;
#pragma unroll
    for (int i = 0; i < KK; i++) gs += g_knss[n * KK + i];
    float sc = 1.f / fmaxf(sqrtf(gs), EPSV);
    size_t base = (size_t)n * KK * CC + (size_t)blockIdx.y * 2048;
#pragma unroll
    for (int q = 0; q < 8; q++) out[base + t + 256 * q] *= sc;
}

// ---------------------------------------------------------------------------
extern "C" void kernel_launch(void* const* d_in, const int* in_sizes, int n_in,
                              void* d_out, int out_size) {
    const float* x  = (const float*)d_in[0];   // [48,512,40,40]
    const float* cw = (const float*)d_in[1];   // [64,512]
    const float* aw = (const float*)d_in[2];   // [1,512]
    const float* ab = (const float*)d_in[3];   // [1]
    const float* ct = (const float*)d_in[4];   // [64,512]
    float* out = (float*)d_out;                // [48, 32768]

    k_pixstats<<<300, 256>>>(x, aw, ab);
    k_assign<<<dim3(25, 48), 64>>>(x, cw);
    k_vladgemm<<<dim3(8, 48), 64>>>(x, out);
    k_intranorm<<<NB * KK, 128>>>(out, ct);
    k_globalnorm<<<dim3(48, 16), 256>>>(out);
}